// round 2
// baseline (speedup 1.0000x reference)
#include <cuda_runtime.h>
#include <cuda_bf16.h>

// Problem constants
#define BSZ   4
#define SEQ   4096
#define BL    16384          // BSZ*SEQ tokens
#define DM    512            // d_model
#define DI    1024           // d_inner
#define DH    512            // d_half
#define DTR   32             // dt_rank
#define NST   16             // d_state
#define XDB   64             // dt_rank + 2*d_state

// Scratch (single pooled static device array: allocation-free at runtime)
// layout: xz[BL*DI] | xc[BL*DH] | ycat[BL*DI] | delta[BL*DH] | Bp[BL*NST] | Cp[BL*NST]
#define OFF_XZ    0
#define OFF_XC    ((size_t)BL * DI)
#define OFF_YCAT  (OFF_XC + (size_t)BL * DH)
#define OFF_DELTA (OFF_YCAT + (size_t)BL * DI)
#define OFF_BP    (OFF_DELTA + (size_t)BL * DH)
#define OFF_CP    (OFF_BP + (size_t)BL * NST)
#define POOL_SZ   (OFF_CP + (size_t)BL * NST)
__device__ float g_pool[POOL_SZ];

// ---------------------------------------------------------------------------
// SGEMM: C[M,N] = A[M,K] @ B[N,K]^T   (both row-major, K contiguous)
// 128x128 tile, BK=8, 256 threads, 8x8 per-thread, double-buffered smem.
// ---------------------------------------------------------------------------
__global__ __launch_bounds__(256) void sgemm_nt(
    const float* __restrict__ A, const float* __restrict__ B,
    float* __restrict__ C, int M, int N, int K)
{
    __shared__ float As[2][8][128];
    __shared__ float Bs[2][8][128];

    const int tid = threadIdx.x;
    const int bm = blockIdx.y * 128;
    const int bn = blockIdx.x * 128;

    const int lrow = tid >> 1;            // 0..127
    const int lcol = (tid & 1) << 2;      // 0 or 4

    const float* Aptr = A + (size_t)(bm + lrow) * K + lcol;
    const float* Bptr = B + (size_t)(bn + lrow) * K + lcol;

    const int tx = tid & 15;              // 0..15 -> n
    const int ty = tid >> 4;              // 0..15 -> m
    const int tm0 = ty * 8;
    const int tn0 = tx * 8;

    float acc[8][8];
#pragma unroll
    for (int i = 0; i < 8; i++)
#pragma unroll
        for (int j = 0; j < 8; j++) acc[i][j] = 0.f;

    // preload tile 0
    {
        float4 ra = *(const float4*)(Aptr);
        float4 rb = *(const float4*)(Bptr);
        As[0][lcol + 0][lrow] = ra.x; As[0][lcol + 1][lrow] = ra.y;
        As[0][lcol + 2][lrow] = ra.z; As[0][lcol + 3][lrow] = ra.w;
        Bs[0][lcol + 0][lrow] = rb.x; Bs[0][lcol + 1][lrow] = rb.y;
        Bs[0][lcol + 2][lrow] = rb.z; Bs[0][lcol + 3][lrow] = rb.w;
    }
    __syncthreads();

    int buf = 0;
    for (int kt = 0; kt < K; kt += 8) {
        const bool more = (kt + 8) < K;
        float4 ra, rb;
        if (more) {
            ra = *(const float4*)(Aptr + kt + 8);
            rb = *(const float4*)(Bptr + kt + 8);
        }
#pragma unroll
        for (int kk = 0; kk < 8; kk++) {
            float4 a0 = *(const float4*)&As[buf][kk][tm0];
            float4 a1 = *(const float4*)&As[buf][kk][tm0 + 4];
            float4 b0 = *(const float4*)&Bs[buf][kk][tn0];
            float4 b1 = *(const float4*)&Bs[buf][kk][tn0 + 4];
            float av[8] = {a0.x, a0.y, a0.z, a0.w, a1.x, a1.y, a1.z, a1.w};
            float bw[8] = {b0.x, b0.y, b0.z, b0.w, b1.x, b1.y, b1.z, b1.w};
#pragma unroll
            for (int i = 0; i < 8; i++)
#pragma unroll
                for (int j = 0; j < 8; j++)
                    acc[i][j] = fmaf(av[i], bw[j], acc[i][j]);
        }
        if (more) {
            int nb = buf ^ 1;
            As[nb][lcol + 0][lrow] = ra.x; As[nb][lcol + 1][lrow] = ra.y;
            As[nb][lcol + 2][lrow] = ra.z; As[nb][lcol + 3][lrow] = ra.w;
            Bs[nb][lcol + 0][lrow] = rb.x; Bs[nb][lcol + 1][lrow] = rb.y;
            Bs[nb][lcol + 2][lrow] = rb.z; Bs[nb][lcol + 3][lrow] = rb.w;
            __syncthreads();
            buf = nb;
        }
    }

#pragma unroll
    for (int i = 0; i < 8; i++) {
        float* Crow = C + (size_t)(bm + tm0 + i) * N + bn + tn0;
        *(float4*)Crow       = make_float4(acc[i][0], acc[i][1], acc[i][2], acc[i][3]);
        *(float4*)(Crow + 4) = make_float4(acc[i][4], acc[i][5], acc[i][6], acc[i][7]);
    }
}

// ---------------------------------------------------------------------------
// Depthwise conv(k=4, pad l=1 r=2) + SiLU for both halves of xz.
// x half -> xc; z half -> ycat[:, 512:1024]
// One thread per 4 channels of one token.
// ---------------------------------------------------------------------------
__global__ __launch_bounds__(256) void conv_silu_kernel(
    const float* __restrict__ xz,
    const float* __restrict__ cxw, const float* __restrict__ cxb,
    const float* __restrict__ czw, const float* __restrict__ czb,
    float* __restrict__ xcout, float* __restrict__ ycat)
{
    int idx = blockIdx.x * 256 + threadIdx.x;     // 0 .. BL*256-1
    int c4 = idx & 255;
    int t  = idx >> 8;                            // token index b*SEQ+l
    int l  = t & (SEQ - 1);
    int c  = c4 * 4;

    const float* base = xz + (size_t)t * DI + c;
    float4 z4 = make_float4(0.f, 0.f, 0.f, 0.f);
    float4 s0 = (l >= 1)       ? *(const float4*)(base - DI)     : z4;
    float4 s1 =                  *(const float4*)(base);
    float4 s2 = (l + 1 < SEQ)  ? *(const float4*)(base + DI)     : z4;
    float4 s3 = (l + 2 < SEQ)  ? *(const float4*)(base + 2 * DI) : z4;

    float r0[4], r1[4], r2[4], r3[4];
    *(float4*)r0 = s0; *(float4*)r1 = s1; *(float4*)r2 = s2; *(float4*)r3 = s3;

    const bool isx = (c < DH);
    const int  cc  = isx ? c : (c - DH);
    const float* w  = (isx ? cxw : czw) + cc * 4;
    const float* bb = (isx ? cxb : czb) + cc;

    float out[4];
#pragma unroll
    for (int i = 0; i < 4; i++) {
        float v = bb[i]
                + w[i * 4 + 0] * r0[i]
                + w[i * 4 + 1] * r1[i]
                + w[i * 4 + 2] * r2[i]
                + w[i * 4 + 3] * r3[i];
        float sg = __fdividef(1.f, 1.f + __expf(-v));
        out[i] = v * sg;
    }
    if (isx) *(float4*)(xcout + (size_t)t * DH + c) = *(float4*)out;
    else     *(float4*)(ycat  + (size_t)t * DI + c) = *(float4*)out;  // c already in [512,1024)
}

// ---------------------------------------------------------------------------
// Fused: x_dbl = xc @ x_proj_w^T (64 out), LayerNorm(64), split -> Bp/Cp,
//        dt = clip(dt_raw @ dt_proj_w^T, -6, 6), delta = softplus(dt + bias)
// One block handles 16 tokens, 256 threads.
// ---------------------------------------------------------------------------
__global__ __launch_bounds__(256) void k3_kernel(
    const float* __restrict__ xc,  const float* __restrict__ xpw,
    const float* __restrict__ dtw, const float* __restrict__ dtb,
    const float* __restrict__ lnw, const float* __restrict__ lnb,
    float* __restrict__ delta, float* __restrict__ Bp, float* __restrict__ Cp)
{
    __shared__ float s_xc[16][DH];
    __shared__ float s_db[16][XDB];

    const int tid = threadIdx.x;
    const size_t tok0 = (size_t)blockIdx.x * 16;

    // load 16 token rows of xc (8192 floats)
    {
        const float4* src = (const float4*)(xc + tok0 * DH);
        float4* dst = (float4*)&s_xc[0][0];
#pragma unroll
        for (int i = 0; i < 8; i++) dst[tid + i * 256] = src[tid + i * 256];
    }
    __syncthreads();

    // x_dbl: 16 tokens x 64 outputs; thread = (j, 4-token group)
    {
        const int j  = tid & 63;
        const int tg = tid >> 6;   // 0..3
        const float4* wr = (const float4*)(xpw + (size_t)j * DH);
        const float4* x0 = (const float4*)&s_xc[tg * 4 + 0][0];
        const float4* x1 = (const float4*)&s_xc[tg * 4 + 1][0];
        const float4* x2 = (const float4*)&s_xc[tg * 4 + 2][0];
        const float4* x3 = (const float4*)&s_xc[tg * 4 + 3][0];
        float a0 = 0.f, a1 = 0.f, a2 = 0.f, a3 = 0.f;
#pragma unroll 4
        for (int k = 0; k < DH / 4; k++) {
            float4 w4 = wr[k];
            float4 v0 = x0[k], v1 = x1[k], v2 = x2[k], v3 = x3[k];
            a0 += w4.x * v0.x + w4.y * v0.y + w4.z * v0.z + w4.w * v0.w;
            a1 += w4.x * v1.x + w4.y * v1.y + w4.z * v1.z + w4.w * v1.w;
            a2 += w4.x * v2.x + w4.y * v2.y + w4.z * v2.z + w4.w * v2.w;
            a3 += w4.x * v3.x + w4.y * v3.y + w4.z * v3.z + w4.w * v3.w;
        }
        s_db[tg * 4 + 0][j] = a0;
        s_db[tg * 4 + 1][j] = a1;
        s_db[tg * 4 + 2][j] = a2;
        s_db[tg * 4 + 3][j] = a3;
    }
    __syncthreads();

    // LayerNorm over 64 per token: 16 lanes per token, 4 values each
    {
        const int tok = tid >> 4;
        const int q   = tid & 15;
        const int j0  = q * 4;
        float v0 = s_db[tok][j0], v1 = s_db[tok][j0 + 1];
        float v2 = s_db[tok][j0 + 2], v3 = s_db[tok][j0 + 3];
        float s = v0 + v1 + v2 + v3;
        s += __shfl_xor_sync(0xffffffffu, s, 1);
        s += __shfl_xor_sync(0xffffffffu, s, 2);
        s += __shfl_xor_sync(0xffffffffu, s, 4);
        s += __shfl_xor_sync(0xffffffffu, s, 8);
        float mu = s * (1.f / 64.f);
        float d0 = v0 - mu, d1 = v1 - mu, d2 = v2 - mu, d3 = v3 - mu;
        float sq = d0 * d0 + d1 * d1 + d2 * d2 + d3 * d3;
        sq += __shfl_xor_sync(0xffffffffu, sq, 1);
        sq += __shfl_xor_sync(0xffffffffu, sq, 2);
        sq += __shfl_xor_sync(0xffffffffu, sq, 4);
        sq += __shfl_xor_sync(0xffffffffu, sq, 8);
        float rstd = rsqrtf(sq * (1.f / 64.f) + 1e-5f);
        float o[4];
        o[0] = d0 * rstd * lnw[j0]     + lnb[j0];
        o[1] = d1 * rstd * lnw[j0 + 1] + lnb[j0 + 1];
        o[2] = d2 * rstd * lnw[j0 + 2] + lnb[j0 + 2];
        o[3] = d3 * rstd * lnw[j0 + 3] + lnb[j0 + 3];
        s_db[tok][j0] = o[0]; s_db[tok][j0 + 1] = o[1];
        s_db[tok][j0 + 2] = o[2]; s_db[tok][j0 + 3] = o[3];
        if (q >= 8) {   // j0 in [32,64) -> Bp / Cp
            size_t tk = tok0 + tok;
            int base = j0 - DTR;  // 0..31
#pragma unroll
            for (int i = 0; i < 4; i++) {
                int jj = base + i;
                if (jj < NST) Bp[tk * NST + jj]         = o[i];
                else          Cp[tk * NST + (jj - NST)] = o[i];
            }
        }
    }
    __syncthreads();

    // dt projection + softplus: thread -> channel d (two halves)
    {
#pragma unroll
        for (int half = 0; half < 2; half++) {
            const int dch = tid + half * 256;
            const float4* wr = (const float4*)(dtw + (size_t)dch * DTR);
            float4 w4[8];
#pragma unroll
            for (int i = 0; i < 8; i++) w4[i] = wr[i];
            const float bias = dtb[dch];
#pragma unroll
            for (int tok = 0; tok < 16; tok++) {
                const float4* xr = (const float4*)&s_db[tok][0];
                float acc = 0.f;
#pragma unroll
                for (int i = 0; i < 8; i++) {
                    float4 x4 = xr[i];
                    acc += w4[i].x * x4.x + w4[i].y * x4.y
                         + w4[i].z * x4.z + w4[i].w * x4.w;
                }
                float v = fminf(fmaxf(acc, -6.f), 6.f) + bias;
                float sp = fmaxf(v, 0.f) + log1pf(__expf(-fabsf(v)));
                delta[(tok0 + tok) * (size_t)DH + dch] = sp;
            }
        }
    }
}

// ---------------------------------------------------------------------------
// Selective scan. Channel (b,d) = 16 lanes (one per state), 2 channels/warp,
// 16 channels per 256-thread block, 128 blocks for 2048 channels.
// Double-buffered 4-step register prefetch.
// ---------------------------------------------------------------------------
__global__ __launch_bounds__(256) void scan_kernel(
    const float* __restrict__ delta, const float* __restrict__ xc,
    const float* __restrict__ Bp,    const float* __restrict__ Cp,
    const float* __restrict__ A_log, const float* __restrict__ D_param,
    float* __restrict__ ycat)
{
    const int tid = threadIdx.x;
    const int ch  = blockIdx.x * 16 + (tid >> 4);   // 0..2047
    const int n   = tid & 15;
    const int b   = ch >> 9;
    const int d   = ch & 511;

    const float a  = -__expf(A_log[d * NST + n]);
    const float Dd = D_param[d];

    const float* dl = delta + ((size_t)b * SEQ) * DH + d;
    const float* ul = xc    + ((size_t)b * SEQ) * DH + d;
    const float* Bl = Bp    + ((size_t)b * SEQ) * NST + n;
    const float* Cl = Cp    + ((size_t)b * SEQ) * NST + n;
    float*       yl = ycat  + ((size_t)b * SEQ) * DI + d;

    float h = 0.f;
    float dv[2][4], uv[2][4], bv[2][4], cv[2][4];

#pragma unroll
    for (int i = 0; i < 4; i++) {
        dv[0][i] = dl[i * DH];  uv[0][i] = ul[i * DH];
        bv[0][i] = Bl[i * NST]; cv[0][i] = Cl[i * NST];
    }

    for (int l0 = 0; l0 < SEQ; l0 += 4) {
        const int cur = (l0 >> 2) & 1;
        const int nxt = cur ^ 1;
        if (l0 + 4 < SEQ) {
            const float* dn = dl + 4 * DH;
            const float* un = ul + 4 * DH;
            const float* bn = Bl + 4 * NST;
            const float* cn = Cl + 4 * NST;
#pragma unroll
            for (int i = 0; i < 4; i++) {
                dv[nxt][i] = dn[i * DH];  uv[nxt][i] = un[i * DH];
                bv[nxt][i] = bn[i * NST]; cv[nxt][i] = cn[i * NST];
            }
        }
#pragma unroll
        for (int i = 0; i < 4; i++) {
            float dvi = dv[cur][i];
            float da  = __expf(dvi * a);
            h = fmaf(da, h, dvi * uv[cur][i] * bv[cur][i]);
            float p = h * cv[cur][i];
            p += __shfl_xor_sync(0xffffffffu, p, 8);
            p += __shfl_xor_sync(0xffffffffu, p, 4);
            p += __shfl_xor_sync(0xffffffffu, p, 2);
            p += __shfl_xor_sync(0xffffffffu, p, 1);
            if (n == 0) yl[i * DI] = fmaf(Dd, uv[cur][i], p);
        }
        dl += 4 * DH; ul += 4 * DH; Bl += 4 * NST; Cl += 4 * NST; yl += 4 * DI;
    }
}

// ---------------------------------------------------------------------------
extern "C" void kernel_launch(void* const* d_in, const int* in_sizes, int n_in,
                              void* d_out, int out_size)
{
    const float* hs   = (const float*)d_in[0];
    const float* ipw  = (const float*)d_in[1];
    const float* xpw  = (const float*)d_in[2];
    const float* dtw  = (const float*)d_in[3];
    const float* dtb  = (const float*)d_in[4];
    const float* alog = (const float*)d_in[5];
    const float* Dp   = (const float*)d_in[6];
    const float* cxw  = (const float*)d_in[7];
    const float* cxb  = (const float*)d_in[8];
    const float* czw  = (const float*)d_in[9];
    const float* czb  = (const float*)d_in[10];
    const float* lnw  = (const float*)d_in[11];
    const float* lnb  = (const float*)d_in[12];
    const float* opw  = (const float*)d_in[13];

    float* pool = nullptr;
    cudaGetSymbolAddress((void**)&pool, g_pool);
    float* xz    = pool + OFF_XZ;
    float* xc    = pool + OFF_XC;
    float* ycat  = pool + OFF_YCAT;
    float* delta = pool + OFF_DELTA;
    float* Bpp   = pool + OFF_BP;
    float* Cpp   = pool + OFF_CP;

    // 1) xz = hidden @ in_proj_w^T         [16384,1024]
    sgemm_nt<<<dim3(DI / 128, BL / 128), 256>>>(hs, ipw, xz, BL, DI, DM);
    // 2) depthwise conv + silu (x -> xc, z -> ycat[:,512:])
    conv_silu_kernel<<<BL, 256>>>(xz, cxw, cxb, czw, czb, xc, ycat);
    // 3) x_proj + LN + dt_proj + softplus
    k3_kernel<<<BL / 16, 256>>>(xc, xpw, dtw, dtb, lnw, lnb, delta, Bpp, Cpp);
    // 4) selective scan -> ycat[:, :512] (includes +xc*D)
    scan_kernel<<<128, 256>>>(delta, xc, Bpp, Cpp, alog, Dp, ycat);
    // 5) out = ycat @ out_proj_w^T         [16384,512]
    sgemm_nt<<<dim3(DM / 128, BL / 128), 256>>>(ycat, opw, (float*)d_out, BL, DM, DI);
}

// round 4
// speedup vs baseline: 1.2105x; 1.2105x over previous
#include <cuda_runtime.h>
#include <cuda_bf16.h>
#include <cstdint>

// Problem constants
#define BSZ   4
#define SEQ   4096
#define BL    16384          // BSZ*SEQ tokens
#define DM    512            // d_model
#define DI    1024           // d_inner
#define DH    512            // d_half
#define DTR   32             // dt_rank
#define NST   16             // d_state
#define XDB   64             // dt_rank + 2*d_state

// Scratch (single pooled static device array: allocation-free at runtime)
#define OFF_XZ    0
#define OFF_XC    ((size_t)BL * DI)
#define OFF_YCAT  (OFF_XC + (size_t)BL * DH)
#define OFF_DELTA (OFF_YCAT + (size_t)BL * DI)
#define OFF_BP    (OFF_DELTA + (size_t)BL * DH)
#define OFF_CP    (OFF_BP + (size_t)BL * NST)
#define POOL_SZ   (OFF_CP + (size_t)BL * NST)
__device__ float g_pool[POOL_SZ];

// ---------------------------------------------------------------------------
// TF32 tensor-core GEMM: C[M,N] = A[M,K] @ B[N,K]^T (row-major, K contiguous)
// Block: 128x128x16, 256 threads (8 warps, 2x4), warp tile 64x32 via
// mma.sync.m16n8k8.tf32. Double-buffered smem, fp32->tf32 on smem fill.
// Requires M%128==0, N%128==0, K%16==0 (true for all uses here).
// ---------------------------------------------------------------------------
__device__ __forceinline__ uint32_t f2tf32(float x) {
    uint32_t y;
    asm("cvt.rna.tf32.f32 %0, %1;" : "=r"(y) : "f"(x));
    return y;
}

#define SMS 136   // smem row stride (136 % 32 == 8 -> conflict-free frag loads)

__global__ __launch_bounds__(256) void gemm_tf32_nt(
    const float* __restrict__ A, const float* __restrict__ B,
    float* __restrict__ C, int M, int N, int K)
{
    __shared__ uint32_t As[2][16][SMS];
    __shared__ uint32_t Bs[2][16][SMS];

    const int tid  = threadIdx.x;
    const int lane = tid & 31;
    const int wid  = tid >> 5;
    const int bm = blockIdx.y * 128;
    const int bn = blockIdx.x * 128;

    // warp tile: 2 warps along M (64 rows), 4 along N (32 cols)
    const int wm = (wid & 1) * 64;
    const int wn = (wid >> 1) * 32;
    const int r = lane >> 2;      // group id 0..7
    const int c = lane & 3;       // thread-in-group 0..3

    // global load mapping: each thread loads 8 consecutive K-floats of one row
    const int lrow  = tid >> 1;          // 0..127
    const int lcol8 = (tid & 1) * 8;     // 0 or 8
    const float* Aptr = A + (size_t)(bm + lrow) * K + lcol8;
    const float* Bptr = B + (size_t)(bn + lrow) * K + lcol8;

    float acc[4][4][4];
#pragma unroll
    for (int i = 0; i < 4; i++)
#pragma unroll
        for (int j = 0; j < 4; j++)
#pragma unroll
            for (int q = 0; q < 4; q++) acc[i][j][q] = 0.f;

    float4 ra0, ra1, rb0, rb1;
    // preload tile 0
    ra0 = *(const float4*)(Aptr);
    ra1 = *(const float4*)(Aptr + 4);
    rb0 = *(const float4*)(Bptr);
    rb1 = *(const float4*)(Bptr + 4);
    {
        float av[8] = {ra0.x, ra0.y, ra0.z, ra0.w, ra1.x, ra1.y, ra1.z, ra1.w};
        float bv[8] = {rb0.x, rb0.y, rb0.z, rb0.w, rb1.x, rb1.y, rb1.z, rb1.w};
#pragma unroll
        for (int i = 0; i < 8; i++) {
            As[0][lcol8 + i][lrow] = f2tf32(av[i]);
            Bs[0][lcol8 + i][lrow] = f2tf32(bv[i]);
        }
    }
    __syncthreads();

    int buf = 0;
    for (int kt = 0; kt < K; kt += 16) {
        const bool more = (kt + 16) < K;
        if (more) {
            ra0 = *(const float4*)(Aptr + kt + 16);
            ra1 = *(const float4*)(Aptr + kt + 20);
            rb0 = *(const float4*)(Bptr + kt + 16);
            rb1 = *(const float4*)(Bptr + kt + 20);
        }

#pragma unroll
        for (int kk = 0; kk < 2; kk++) {
            const int k0 = kk * 8;
            uint32_t af[4][4], bf[4][2];
#pragma unroll
            for (int i = 0; i < 4; i++) {
                const int m0 = wm + i * 16;
                af[i][0] = As[buf][k0 + c    ][m0 + r];
                af[i][1] = As[buf][k0 + c    ][m0 + r + 8];
                af[i][2] = As[buf][k0 + c + 4][m0 + r];
                af[i][3] = As[buf][k0 + c + 4][m0 + r + 8];
            }
#pragma unroll
            for (int j = 0; j < 4; j++) {
                const int n0 = wn + j * 8;
                bf[j][0] = Bs[buf][k0 + c    ][n0 + r];
                bf[j][1] = Bs[buf][k0 + c + 4][n0 + r];
            }
#pragma unroll
            for (int i = 0; i < 4; i++)
#pragma unroll
                for (int j = 0; j < 4; j++) {
                    asm volatile(
                        "mma.sync.aligned.m16n8k8.row.col.f32.tf32.tf32.f32 "
                        "{%0,%1,%2,%3}, {%4,%5,%6,%7}, {%8,%9}, {%0,%1,%2,%3};"
                        : "+f"(acc[i][j][0]), "+f"(acc[i][j][1]),
                          "+f"(acc[i][j][2]), "+f"(acc[i][j][3])
                        : "r"(af[i][0]), "r"(af[i][1]), "r"(af[i][2]), "r"(af[i][3]),
                          "r"(bf[j][0]), "r"(bf[j][1]));
                }
        }

        if (more) {
            const int nb = buf ^ 1;
            float av[8] = {ra0.x, ra0.y, ra0.z, ra0.w, ra1.x, ra1.y, ra1.z, ra1.w};
            float bv[8] = {rb0.x, rb0.y, rb0.z, rb0.w, rb1.x, rb1.y, rb1.z, rb1.w};
#pragma unroll
            for (int i = 0; i < 8; i++) {
                As[nb][lcol8 + i][lrow] = f2tf32(av[i]);
                Bs[nb][lcol8 + i][lrow] = f2tf32(bv[i]);
            }
            __syncthreads();
            buf = nb;
        }
    }

    // epilogue: c0:(r,2c) c1:(r,2c+1) c2:(r+8,2c) c3:(r+8,2c+1)
#pragma unroll
    for (int i = 0; i < 4; i++) {
        const int row0 = bm + wm + i * 16 + r;
#pragma unroll
        for (int j = 0; j < 4; j++) {
            const int col = bn + wn + j * 8 + 2 * c;
            *(float2*)&C[(size_t)row0 * N + col] =
                make_float2(acc[i][j][0], acc[i][j][1]);
            *(float2*)&C[(size_t)(row0 + 8) * N + col] =
                make_float2(acc[i][j][2], acc[i][j][3]);
        }
    }
}

// ---------------------------------------------------------------------------
// Depthwise conv(k=4, pad l=1 r=2) + SiLU for both halves of xz.
// x half -> xc; z half -> ycat[:, 512:1024]
// ---------------------------------------------------------------------------
__global__ __launch_bounds__(256) void conv_silu_kernel(
    const float* __restrict__ xz,
    const float* __restrict__ cxw, const float* __restrict__ cxb,
    const float* __restrict__ czw, const float* __restrict__ czb,
    float* __restrict__ xcout, float* __restrict__ ycat)
{
    int idx = blockIdx.x * 256 + threadIdx.x;
    int c4 = idx & 255;
    int t  = idx >> 8;
    int l  = t & (SEQ - 1);
    int c  = c4 * 4;

    const float* base = xz + (size_t)t * DI + c;
    float4 z4 = make_float4(0.f, 0.f, 0.f, 0.f);
    float4 s0 = (l >= 1)       ? *(const float4*)(base - DI)     : z4;
    float4 s1 =                  *(const float4*)(base);
    float4 s2 = (l + 1 < SEQ)  ? *(const float4*)(base + DI)     : z4;
    float4 s3 = (l + 2 < SEQ)  ? *(const float4*)(base + 2 * DI) : z4;

    float r0[4], r1[4], r2[4], r3[4];
    *(float4*)r0 = s0; *(float4*)r1 = s1; *(float4*)r2 = s2; *(float4*)r3 = s3;

    const bool isx = (c < DH);
    const int  cc  = isx ? c : (c - DH);
    const float* w  = (isx ? cxw : czw) + cc * 4;
    const float* bb = (isx ? cxb : czb) + cc;

    float out[4];
#pragma unroll
    for (int i = 0; i < 4; i++) {
        float v = bb[i]
                + w[i * 4 + 0] * r0[i]
                + w[i * 4 + 1] * r1[i]
                + w[i * 4 + 2] * r2[i]
                + w[i * 4 + 3] * r3[i];
        float sg = __fdividef(1.f, 1.f + __expf(-v));
        out[i] = v * sg;
    }
    if (isx) *(float4*)(xcout + (size_t)t * DH + c) = *(float4*)out;
    else     *(float4*)(ycat  + (size_t)t * DI + c) = *(float4*)out;
}

// ---------------------------------------------------------------------------
// Fused: x_dbl = xc @ x_proj_w^T (64), LN(64), split Bp/Cp,
//        dt = clip(dt_raw @ dt_proj_w^T,-6,6), delta = softplus(dt+bias)
// ---------------------------------------------------------------------------
__global__ __launch_bounds__(256) void k3_kernel(
    const float* __restrict__ xc,  const float* __restrict__ xpw,
    const float* __restrict__ dtw, const float* __restrict__ dtb,
    const float* __restrict__ lnw, const float* __restrict__ lnb,
    float* __restrict__ delta, float* __restrict__ Bp, float* __restrict__ Cp)
{
    __shared__ float s_xc[16][DH];
    __shared__ float s_db[16][XDB];

    const int tid = threadIdx.x;
    const size_t tok0 = (size_t)blockIdx.x * 16;

    {
        const float4* src = (const float4*)(xc + tok0 * DH);
        float4* dst = (float4*)&s_xc[0][0];
#pragma unroll
        for (int i = 0; i < 8; i++) dst[tid + i * 256] = src[tid + i * 256];
    }
    __syncthreads();

    {
        const int j  = tid & 63;
        const int tg = tid >> 6;
        const float4* wr = (const float4*)(xpw + (size_t)j * DH);
        const float4* x0 = (const float4*)&s_xc[tg * 4 + 0][0];
        const float4* x1 = (const float4*)&s_xc[tg * 4 + 1][0];
        const float4* x2 = (const float4*)&s_xc[tg * 4 + 2][0];
        const float4* x3 = (const float4*)&s_xc[tg * 4 + 3][0];
        float a0 = 0.f, a1 = 0.f, a2 = 0.f, a3 = 0.f;
#pragma unroll 4
        for (int k = 0; k < DH / 4; k++) {
            float4 w4 = wr[k];
            float4 v0 = x0[k], v1 = x1[k], v2 = x2[k], v3 = x3[k];
            a0 += w4.x * v0.x + w4.y * v0.y + w4.z * v0.z + w4.w * v0.w;
            a1 += w4.x * v1.x + w4.y * v1.y + w4.z * v1.z + w4.w * v1.w;
            a2 += w4.x * v2.x + w4.y * v2.y + w4.z * v2.z + w4.w * v2.w;
            a3 += w4.x * v3.x + w4.y * v3.y + w4.z * v3.z + w4.w * v3.w;
        }
        s_db[tg * 4 + 0][j] = a0;
        s_db[tg * 4 + 1][j] = a1;
        s_db[tg * 4 + 2][j] = a2;
        s_db[tg * 4 + 3][j] = a3;
    }
    __syncthreads();

    {
        const int tok = tid >> 4;
        const int q   = tid & 15;
        const int j0  = q * 4;
        float v0 = s_db[tok][j0], v1 = s_db[tok][j0 + 1];
        float v2 = s_db[tok][j0 + 2], v3 = s_db[tok][j0 + 3];
        float s = v0 + v1 + v2 + v3;
        s += __shfl_xor_sync(0xffffffffu, s, 1);
        s += __shfl_xor_sync(0xffffffffu, s, 2);
        s += __shfl_xor_sync(0xffffffffu, s, 4);
        s += __shfl_xor_sync(0xffffffffu, s, 8);
        float mu = s * (1.f / 64.f);
        float d0 = v0 - mu, d1 = v1 - mu, d2 = v2 - mu, d3 = v3 - mu;
        float sq = d0 * d0 + d1 * d1 + d2 * d2 + d3 * d3;
        sq += __shfl_xor_sync(0xffffffffu, sq, 1);
        sq += __shfl_xor_sync(0xffffffffu, sq, 2);
        sq += __shfl_xor_sync(0xffffffffu, sq, 4);
        sq += __shfl_xor_sync(0xffffffffu, sq, 8);
        float rstd = rsqrtf(sq * (1.f / 64.f) + 1e-5f);
        float o[4];
        o[0] = d0 * rstd * lnw[j0]     + lnb[j0];
        o[1] = d1 * rstd * lnw[j0 + 1] + lnb[j0 + 1];
        o[2] = d2 * rstd * lnw[j0 + 2] + lnb[j0 + 2];
        o[3] = d3 * rstd * lnw[j0 + 3] + lnb[j0 + 3];
        s_db[tok][j0] = o[0]; s_db[tok][j0 + 1] = o[1];
        s_db[tok][j0 + 2] = o[2]; s_db[tok][j0 + 3] = o[3];
        if (q >= 8) {
            size_t tk = tok0 + tok;
            int base = j0 - DTR;
#pragma unroll
            for (int i = 0; i < 4; i++) {
                int jj = base + i;
                if (jj < NST) Bp[tk * NST + jj]         = o[i];
                else          Cp[tk * NST + (jj - NST)] = o[i];
            }
        }
    }
    __syncthreads();

    {
#pragma unroll
        for (int half = 0; half < 2; half++) {
            const int dch = tid + half * 256;
            const float4* wr = (const float4*)(dtw + (size_t)dch * DTR);
            float4 w4[8];
#pragma unroll
            for (int i = 0; i < 8; i++) w4[i] = wr[i];
            const float bias = dtb[dch];
#pragma unroll
            for (int tok = 0; tok < 16; tok++) {
                const float4* xr = (const float4*)&s_db[tok][0];
                float acc = 0.f;
#pragma unroll
                for (int i = 0; i < 8; i++) {
                    float4 x4 = xr[i];
                    acc += w4[i].x * x4.x + w4[i].y * x4.y
                         + w4[i].z * x4.z + w4[i].w * x4.w;
                }
                float v = fminf(fmaxf(acc, -6.f), 6.f) + bias;
                float sp = fmaxf(v, 0.f) + log1pf(__expf(-fabsf(v)));
                delta[(tok0 + tok) * (size_t)DH + dch] = sp;
            }
        }
    }
}

// ---------------------------------------------------------------------------
// Selective scan. Channel (b,d) = 16 lanes (one per state), 2 channels/warp.
// ---------------------------------------------------------------------------
__global__ __launch_bounds__(256) void scan_kernel(
    const float* __restrict__ delta, const float* __restrict__ xc,
    const float* __restrict__ Bp,    const float* __restrict__ Cp,
    const float* __restrict__ A_log, const float* __restrict__ D_param,
    float* __restrict__ ycat)
{
    const int tid = threadIdx.x;
    const int ch  = blockIdx.x * 16 + (tid >> 4);
    const int n   = tid & 15;
    const int b   = ch >> 9;
    const int d   = ch & 511;

    const float a  = -__expf(A_log[d * NST + n]);
    const float Dd = D_param[d];

    const float* dl = delta + ((size_t)b * SEQ) * DH + d;
    const float* ul = xc    + ((size_t)b * SEQ) * DH + d;
    const float* Bl = Bp    + ((size_t)b * SEQ) * NST + n;
    const float* Cl = Cp    + ((size_t)b * SEQ) * NST + n;
    float*       yl = ycat  + ((size_t)b * SEQ) * DI + d;

    float h = 0.f;
    float dv[2][4], uv[2][4], bv[2][4], cv[2][4];

#pragma unroll
    for (int i = 0; i < 4; i++) {
        dv[0][i] = dl[i * DH];  uv[0][i] = ul[i * DH];
        bv[0][i] = Bl[i * NST]; cv[0][i] = Cl[i * NST];
    }

    for (int l0 = 0; l0 < SEQ; l0 += 4) {
        const int cur = (l0 >> 2) & 1;
        const int nxt = cur ^ 1;
        if (l0 + 4 < SEQ) {
            const float* dn = dl + 4 * DH;
            const float* un = ul + 4 * DH;
            const float* bn = Bl + 4 * NST;
            const float* cn = Cl + 4 * NST;
#pragma unroll
            for (int i = 0; i < 4; i++) {
                dv[nxt][i] = dn[i * DH];  uv[nxt][i] = un[i * DH];
                bv[nxt][i] = bn[i * NST]; cv[nxt][i] = cn[i * NST];
            }
        }
#pragma unroll
        for (int i = 0; i < 4; i++) {
            float dvi = dv[cur][i];
            float da  = __expf(dvi * a);
            h = fmaf(da, h, dvi * uv[cur][i] * bv[cur][i]);
            float p = h * cv[cur][i];
            p += __shfl_xor_sync(0xffffffffu, p, 8);
            p += __shfl_xor_sync(0xffffffffu, p, 4);
            p += __shfl_xor_sync(0xffffffffu, p, 2);
            p += __shfl_xor_sync(0xffffffffu, p, 1);
            if (n == 0) yl[i * DI] = fmaf(Dd, uv[cur][i], p);
        }
        dl += 4 * DH; ul += 4 * DH; Bl += 4 * NST; Cl += 4 * NST; yl += 4 * DI;
    }
}

// ---------------------------------------------------------------------------
extern "C" void kernel_launch(void* const* d_in, const int* in_sizes, int n_in,
                              void* d_out, int out_size)
{
    const float* hs   = (const float*)d_in[0];
    const float* ipw  = (const float*)d_in[1];
    const float* xpw  = (const float*)d_in[2];
    const float* dtw  = (const float*)d_in[3];
    const float* dtb  = (const float*)d_in[4];
    const float* alog = (const float*)d_in[5];
    const float* Dp   = (const float*)d_in[6];
    const float* cxw  = (const float*)d_in[7];
    const float* cxb  = (const float*)d_in[8];
    const float* czw  = (const float*)d_in[9];
    const float* czb  = (const float*)d_in[10];
    const float* lnw  = (const float*)d_in[11];
    const float* lnb  = (const float*)d_in[12];
    const float* opw  = (const float*)d_in[13];

    float* pool = nullptr;
    cudaGetSymbolAddress((void**)&pool, g_pool);
    float* xz    = pool + OFF_XZ;
    float* xc    = pool + OFF_XC;
    float* ycat  = pool + OFF_YCAT;
    float* delta = pool + OFF_DELTA;
    float* Bpp   = pool + OFF_BP;
    float* Cpp   = pool + OFF_CP;

    // 1) xz = hidden @ in_proj_w^T         [16384,1024]
    gemm_tf32_nt<<<dim3(DI / 128, BL / 128), 256>>>(hs, ipw, xz, BL, DI, DM);
    // 2) depthwise conv + silu (x -> xc, z -> ycat[:,512:])
    conv_silu_kernel<<<BL, 256>>>(xz, cxw, cxb, czw, czb, xc, ycat);
    // 3) x_proj + LN + dt_proj + softplus
    k3_kernel<<<BL / 16, 256>>>(xc, xpw, dtw, dtb, lnw, lnb, delta, Bpp, Cpp);
    // 4) selective scan -> ycat[:, :512] (includes +xc*D)
    scan_kernel<<<128, 256>>>(delta, xc, Bpp, Cpp, alog, Dp, ycat);
    // 5) out = ycat @ out_proj_w^T         [16384,512]
    gemm_tf32_nt<<<dim3(DM / 128, BL / 128), 256>>>(ycat, opw, (float*)d_out, BL, DM, DI);
}

// round 7
// speedup vs baseline: 1.2615x; 1.0422x over previous
#include <cuda_runtime.h>
#include <cuda_bf16.h>
#include <cstdint>

// Problem constants
#define BSZ   4
#define SEQ   4096
#define BL    16384          // BSZ*SEQ tokens
#define DM    512            // d_model
#define DI    1024           // d_inner
#define DH    512            // d_half
#define DTR   32             // dt_rank
#define NST   16             // d_state
#define XDB   64             // dt_rank + 2*d_state

// Scratch pool (static device global: allocation-free at runtime)
#define OFF_XZ    0
#define OFF_XC    ((size_t)BL * DI)
#define OFF_YCAT  (OFF_XC + (size_t)BL * DH)
#define OFF_DELTA (OFF_YCAT + (size_t)BL * DI)
#define OFF_BP    (OFF_DELTA + (size_t)BL * DH)
#define OFF_CP    (OFF_BP + (size_t)BL * NST)
#define OFF_RW    (OFF_CP + (size_t)BL * NST)
#define POOL_SZ   (OFF_RW + (size_t)DI * DM)
__device__ float g_pool[POOL_SZ];

// ---------------------------------------------------------------------------
// Helpers
// ---------------------------------------------------------------------------
__device__ __forceinline__ uint32_t f2tf32(float x) {
    uint32_t y;
    asm("cvt.rna.tf32.f32 %0, %1;" : "=r"(y) : "f"(x));
    return y;
}
__device__ __forceinline__ uint32_t sm_u32(const void* p) {
    return (uint32_t)__cvta_generic_to_shared(p);
}
__device__ __forceinline__ void cp16(uint32_t dst, const void* src) {
    asm volatile("cp.async.cg.shared.global [%0], [%1], 16;" :: "r"(dst), "l"(src));
}

// ---------------------------------------------------------------------------
// Pre-round fp32 -> tf32 (rna) so the MMA consumes exactly-tf32 values.
// ---------------------------------------------------------------------------
__global__ __launch_bounds__(256) void round_tf32_kernel(
    const float* __restrict__ in, float* __restrict__ out, int n4)
{
    int i = blockIdx.x * 256 + threadIdx.x;
    if (i < n4) {
        float4 v = ((const float4*)in)[i];
        uint4 o;
        o.x = f2tf32(v.x); o.y = f2tf32(v.y);
        o.z = f2tf32(v.z); o.w = f2tf32(v.w);
        ((uint4*)out)[i] = o;
    }
}

// ---------------------------------------------------------------------------
// TF32 mma.sync GEMM (sm_100-portable path; tcgen05 unavailable on .target sm_100)
// C[M,N] = A[M,K] @ B[N,K]^T, row-major, K contiguous, inputs pre-rounded tf32.
// CTA 128x128, 4 warps (2x2), warp tile 64x64, BK=16, 4-stage cp.async.
// Smem layout: [row][k] with row stride 20 words -> conflict-free frag loads.
// Requires M%128==0, N%128==0, K%16==0.
// ---------------------------------------------------------------------------
#define WG_RS     20                       // smem row stride in words
#define WG_STAGE  (128 * WG_RS)            // words per operand per stage
#define WG_STAGES 4
#define WG_SMEM_BYTES (WG_STAGES * 2 * WG_STAGE * 4)   // 81920

__global__ __launch_bounds__(128, 1) void gemm_tf32_mma(
    const float* __restrict__ A, const float* __restrict__ B,
    float* __restrict__ C, int M, int N, int K)
{
    extern __shared__ uint32_t smw[];
    const int tid  = threadIdx.x;
    const int lane = tid & 31;
    const int wid  = tid >> 5;
    const int bm = blockIdx.y * 128;
    const int bn = blockIdx.x * 128;
    const int NC = K / 16;

    const int wm = (wid & 1) * 64;
    const int wn = (wid >> 1) * 64;
    const int r = lane >> 2;      // 0..7
    const int c = lane & 3;       // 0..3

    const uint32_t smb = sm_u32(smw);

    // cp.async fill: per stage, each thread moves 4 A-chunks + 4 B-chunks (16B each)
    auto load_chunk = [&](int chunk, int stage) {
        const int k0 = chunk * 16;
        const uint32_t aB = smb + stage * (2 * WG_STAGE) * 4;
        const uint32_t bB = aB + WG_STAGE * 4;
#pragma unroll
        for (int j = 0; j < 4; j++) {
            int idx = tid + j * 128;          // 0..511
            int row = idx >> 2;
            int seg = idx & 3;
            cp16(aB + (row * WG_RS + seg * 4) * 4,
                 A + (size_t)(bm + row) * K + k0 + seg * 4);
            cp16(bB + (row * WG_RS + seg * 4) * 4,
                 B + (size_t)(bn + row) * K + k0 + seg * 4);
        }
    };

    float acc[4][8][4];
#pragma unroll
    for (int i = 0; i < 4; i++)
#pragma unroll
        for (int j = 0; j < 8; j++)
#pragma unroll
            for (int q = 0; q < 4; q++) acc[i][j][q] = 0.f;

    // prologue: 3 stages in flight
#pragma unroll
    for (int s = 0; s < WG_STAGES - 1; s++) {
        load_chunk(s, s);
        asm volatile("cp.async.commit_group;" ::: "memory");
    }

    for (int i = 0; i < NC; i++) {
        asm volatile("cp.async.wait_group %0;" :: "n"(WG_STAGES - 2) : "memory");
        __syncthreads();

        // prefetch stage i+3 into slot (i+3)%4 (freed last iter); empty commit at tail
        if (i + WG_STAGES - 1 < NC)
            load_chunk(i + WG_STAGES - 1, (i + WG_STAGES - 1) & (WG_STAGES - 1));
        asm volatile("cp.async.commit_group;" ::: "memory");

        const int st = i & (WG_STAGES - 1);
        const uint32_t* As = smw + st * 2 * WG_STAGE;
        const uint32_t* Bs = As + WG_STAGE;

#pragma unroll
        for (int kk = 0; kk < 16; kk += 8) {
            uint32_t af[4][4], bf[8][2];
#pragma unroll
            for (int ii = 0; ii < 4; ii++) {
                const int m0 = wm + ii * 16;
                af[ii][0] = As[(m0 + r)     * WG_RS + kk + c];
                af[ii][1] = As[(m0 + r + 8) * WG_RS + kk + c];
                af[ii][2] = As[(m0 + r)     * WG_RS + kk + c + 4];
                af[ii][3] = As[(m0 + r + 8) * WG_RS + kk + c + 4];
            }
#pragma unroll
            for (int jj = 0; jj < 8; jj++) {
                const int n0 = wn + jj * 8;
                bf[jj][0] = Bs[(n0 + r) * WG_RS + kk + c];
                bf[jj][1] = Bs[(n0 + r) * WG_RS + kk + c + 4];
            }
#pragma unroll
            for (int ii = 0; ii < 4; ii++)
#pragma unroll
                for (int jj = 0; jj < 8; jj++) {
                    asm volatile(
                        "mma.sync.aligned.m16n8k8.row.col.f32.tf32.tf32.f32 "
                        "{%0,%1,%2,%3}, {%4,%5,%6,%7}, {%8,%9}, {%0,%1,%2,%3};"
                        : "+f"(acc[ii][jj][0]), "+f"(acc[ii][jj][1]),
                          "+f"(acc[ii][jj][2]), "+f"(acc[ii][jj][3])
                        : "r"(af[ii][0]), "r"(af[ii][1]),
                          "r"(af[ii][2]), "r"(af[ii][3]),
                          "r"(bf[jj][0]), "r"(bf[jj][1]));
                }
        }
        __syncthreads();
    }

    // epilogue: c0:(r,2c) c1:(r,2c+1) c2:(r+8,2c) c3:(r+8,2c+1)
#pragma unroll
    for (int i = 0; i < 4; i++) {
        const int row0 = bm + wm + i * 16 + r;
#pragma unroll
        for (int j = 0; j < 8; j++) {
            const int col = bn + wn + j * 8 + 2 * c;
            *(float2*)&C[(size_t)row0 * N + col] =
                make_float2(acc[i][j][0], acc[i][j][1]);
            *(float2*)&C[(size_t)(row0 + 8) * N + col] =
                make_float2(acc[i][j][2], acc[i][j][3]);
        }
    }
}

// ---------------------------------------------------------------------------
// Depthwise conv(k=4, pad l=1 r=2) + SiLU for both halves of xz.
// x half -> xc; z half -> ycat[:, 512:1024]
// ---------------------------------------------------------------------------
__global__ __launch_bounds__(256) void conv_silu_kernel(
    const float* __restrict__ xz,
    const float* __restrict__ cxw, const float* __restrict__ cxb,
    const float* __restrict__ czw, const float* __restrict__ czb,
    float* __restrict__ xcout, float* __restrict__ ycat)
{
    int idx = blockIdx.x * 256 + threadIdx.x;
    int c4 = idx & 255;
    int t  = idx >> 8;
    int l  = t & (SEQ - 1);
    int c  = c4 * 4;

    const float* base = xz + (size_t)t * DI + c;
    float4 z4 = make_float4(0.f, 0.f, 0.f, 0.f);
    float4 s0 = (l >= 1)       ? *(const float4*)(base - DI)     : z4;
    float4 s1 =                  *(const float4*)(base);
    float4 s2 = (l + 1 < SEQ)  ? *(const float4*)(base + DI)     : z4;
    float4 s3 = (l + 2 < SEQ)  ? *(const float4*)(base + 2 * DI) : z4;

    float r0[4], r1[4], r2[4], r3[4];
    *(float4*)r0 = s0; *(float4*)r1 = s1; *(float4*)r2 = s2; *(float4*)r3 = s3;

    const bool isx = (c < DH);
    const int  cc  = isx ? c : (c - DH);
    const float* w  = (isx ? cxw : czw) + cc * 4;
    const float* bb = (isx ? cxb : czb) + cc;

    float out[4];
#pragma unroll
    for (int i = 0; i < 4; i++) {
        float v = bb[i]
                + w[i * 4 + 0] * r0[i]
                + w[i * 4 + 1] * r1[i]
                + w[i * 4 + 2] * r2[i]
                + w[i * 4 + 3] * r3[i];
        float sg = __fdividef(1.f, 1.f + __expf(-v));
        out[i] = v * sg;
    }
    if (isx) *(float4*)(xcout + (size_t)t * DH + c) = *(float4*)out;
    else     *(float4*)(ycat  + (size_t)t * DI + c) = *(float4*)out;
}

// ---------------------------------------------------------------------------
// Fused: x_dbl = xc @ x_proj_w^T (64), LN(64), split Bp/Cp,
//        dt = clip(dt_raw @ dt_proj_w^T,-6,6), delta = softplus(dt+bias)
// ---------------------------------------------------------------------------
__global__ __launch_bounds__(256) void k3_kernel(
    const float* __restrict__ xc,  const float* __restrict__ xpw,
    const float* __restrict__ dtw, const float* __restrict__ dtb,
    const float* __restrict__ lnw, const float* __restrict__ lnb,
    float* __restrict__ delta, float* __restrict__ Bp, float* __restrict__ Cp)
{
    __shared__ float s_xc[16][DH];
    __shared__ float s_db[16][XDB];

    const int tid = threadIdx.x;
    const size_t tok0 = (size_t)blockIdx.x * 16;

    {
        const float4* src = (const float4*)(xc + tok0 * DH);
        float4* dst = (float4*)&s_xc[0][0];
#pragma unroll
        for (int i = 0; i < 8; i++) dst[tid + i * 256] = src[tid + i * 256];
    }
    __syncthreads();

    {
        const int j  = tid & 63;
        const int tg = tid >> 6;
        const float4* wr = (const float4*)(xpw + (size_t)j * DH);
        const float4* x0 = (const float4*)&s_xc[tg * 4 + 0][0];
        const float4* x1 = (const float4*)&s_xc[tg * 4 + 1][0];
        const float4* x2 = (const float4*)&s_xc[tg * 4 + 2][0];
        const float4* x3 = (const float4*)&s_xc[tg * 4 + 3][0];
        float a0 = 0.f, a1 = 0.f, a2 = 0.f, a3 = 0.f;
#pragma unroll 4
        for (int k = 0; k < DH / 4; k++) {
            float4 w4 = wr[k];
            float4 v0 = x0[k], v1 = x1[k], v2 = x2[k], v3 = x3[k];
            a0 += w4.x * v0.x + w4.y * v0.y + w4.z * v0.z + w4.w * v0.w;
            a1 += w4.x * v1.x + w4.y * v1.y + w4.z * v1.z + w4.w * v1.w;
            a2 += w4.x * v2.x + w4.y * v2.y + w4.z * v2.z + w4.w * v2.w;
            a3 += w4.x * v3.x + w4.y * v3.y + w4.z * v3.z + w4.w * v3.w;
        }
        s_db[tg * 4 + 0][j] = a0;
        s_db[tg * 4 + 1][j] = a1;
        s_db[tg * 4 + 2][j] = a2;
        s_db[tg * 4 + 3][j] = a3;
    }
    __syncthreads();

    {
        const int tok = tid >> 4;
        const int q   = tid & 15;
        const int j0  = q * 4;
        float v0 = s_db[tok][j0], v1 = s_db[tok][j0 + 1];
        float v2 = s_db[tok][j0 + 2], v3 = s_db[tok][j0 + 3];
        float s = v0 + v1 + v2 + v3;
        s += __shfl_xor_sync(0xffffffffu, s, 1);
        s += __shfl_xor_sync(0xffffffffu, s, 2);
        s += __shfl_xor_sync(0xffffffffu, s, 4);
        s += __shfl_xor_sync(0xffffffffu, s, 8);
        float mu = s * (1.f / 64.f);
        float d0 = v0 - mu, d1 = v1 - mu, d2 = v2 - mu, d3 = v3 - mu;
        float sq = d0 * d0 + d1 * d1 + d2 * d2 + d3 * d3;
        sq += __shfl_xor_sync(0xffffffffu, sq, 1);
        sq += __shfl_xor_sync(0xffffffffu, sq, 2);
        sq += __shfl_xor_sync(0xffffffffu, sq, 4);
        sq += __shfl_xor_sync(0xffffffffu, sq, 8);
        float rstd = rsqrtf(sq * (1.f / 64.f) + 1e-5f);
        float o[4];
        o[0] = d0 * rstd * lnw[j0]     + lnb[j0];
        o[1] = d1 * rstd * lnw[j0 + 1] + lnb[j0 + 1];
        o[2] = d2 * rstd * lnw[j0 + 2] + lnb[j0 + 2];
        o[3] = d3 * rstd * lnw[j0 + 3] + lnb[j0 + 3];
        s_db[tok][j0] = o[0]; s_db[tok][j0 + 1] = o[1];
        s_db[tok][j0 + 2] = o[2]; s_db[tok][j0 + 3] = o[3];
        if (q >= 8) {
            size_t tk = tok0 + tok;
            int base = j0 - DTR;
#pragma unroll
            for (int i = 0; i < 4; i++) {
                int jj = base + i;
                if (jj < NST) Bp[tk * NST + jj]         = o[i];
                else          Cp[tk * NST + (jj - NST)] = o[i];
            }
        }
    }
    __syncthreads();

    {
#pragma unroll
        for (int half = 0; half < 2; half++) {
            const int dch = tid + half * 256;
            const float4* wr = (const float4*)(dtw + (size_t)dch * DTR);
            float4 w4[8];
#pragma unroll
            for (int i = 0; i < 8; i++) w4[i] = wr[i];
            const float bias = dtb[dch];
#pragma unroll
            for (int tok = 0; tok < 16; tok++) {
                const float4* xr = (const float4*)&s_db[tok][0];
                float acc = 0.f;
#pragma unroll
                for (int i = 0; i < 8; i++) {
                    float4 x4 = xr[i];
                    acc += w4[i].x * x4.x + w4[i].y * x4.y
                         + w4[i].z * x4.z + w4[i].w * x4.w;
                }
                float v = fminf(fmaxf(acc, -6.f), 6.f) + bias;
                float sp = fmaxf(v, 0.f) + log1pf(__expf(-fabsf(v)));
                delta[(tok0 + tok) * (size_t)DH + dch] = sp;
            }
        }
    }
}

// ---------------------------------------------------------------------------
// Selective scan. Channel (b,d) = 16 lanes (one per state), 2 channels/warp.
// ---------------------------------------------------------------------------
__global__ __launch_bounds__(256) void scan_kernel(
    const float* __restrict__ delta, const float* __restrict__ xc,
    const float* __restrict__ Bp,    const float* __restrict__ Cp,
    const float* __restrict__ A_log, const float* __restrict__ D_param,
    float* __restrict__ ycat)
{
    const int tid = threadIdx.x;
    const int ch  = blockIdx.x * 16 + (tid >> 4);
    const int n   = tid & 15;
    const int b   = ch >> 9;
    const int d   = ch & 511;

    const float a  = -__expf(A_log[d * NST + n]);
    const float Dd = D_param[d];

    const float* dl = delta + ((size_t)b * SEQ) * DH + d;
    const float* ul = xc    + ((size_t)b * SEQ) * DH + d;
    const float* Bl = Bp    + ((size_t)b * SEQ) * NST + n;
    const float* Cl = Cp    + ((size_t)b * SEQ) * NST + n;
    float*       yl = ycat  + ((size_t)b * SEQ) * DI + d;

    float h = 0.f;
    float dv[2][4], uv[2][4], bv[2][4], cv[2][4];

#pragma unroll
    for (int i = 0; i < 4; i++) {
        dv[0][i] = dl[i * DH];  uv[0][i] = ul[i * DH];
        bv[0][i] = Bl[i * NST]; cv[0][i] = Cl[i * NST];
    }

    for (int l0 = 0; l0 < SEQ; l0 += 4) {
        const int cur = (l0 >> 2) & 1;
        const int nxt = cur ^ 1;
        if (l0 + 4 < SEQ) {
            const float* dn = dl + 4 * DH;
            const float* un = ul + 4 * DH;
            const float* bn = Bl + 4 * NST;
            const float* cn = Cl + 4 * NST;
#pragma unroll
            for (int i = 0; i < 4; i++) {
                dv[nxt][i] = dn[i * DH];  uv[nxt][i] = un[i * DH];
                bv[nxt][i] = bn[i * NST]; cv[nxt][i] = cn[i * NST];
            }
        }
#pragma unroll
        for (int i = 0; i < 4; i++) {
            float dvi = dv[cur][i];
            float da  = __expf(dvi * a);
            h = fmaf(da, h, dvi * uv[cur][i] * bv[cur][i]);
            float p = h * cv[cur][i];
            p += __shfl_xor_sync(0xffffffffu, p, 8);
            p += __shfl_xor_sync(0xffffffffu, p, 4);
            p += __shfl_xor_sync(0xffffffffu, p, 2);
            p += __shfl_xor_sync(0xffffffffu, p, 1);
            if (n == 0) yl[i * DI] = fmaf(Dd, uv[cur][i], p);
        }
        dl += 4 * DH; ul += 4 * DH; Bl += 4 * NST; Cl += 4 * NST; yl += 4 * DI;
    }
}

// ---------------------------------------------------------------------------
extern "C" void kernel_launch(void* const* d_in, const int* in_sizes, int n_in,
                              void* d_out, int out_size)
{
    const float* hs   = (const float*)d_in[0];
    const float* ipw  = (const float*)d_in[1];
    const float* xpw  = (const float*)d_in[2];
    const float* dtw  = (const float*)d_in[3];
    const float* dtb  = (const float*)d_in[4];
    const float* alog = (const float*)d_in[5];
    const float* Dp   = (const float*)d_in[6];
    const float* cxw  = (const float*)d_in[7];
    const float* cxb  = (const float*)d_in[8];
    const float* czw  = (const float*)d_in[9];
    const float* czb  = (const float*)d_in[10];
    const float* lnw  = (const float*)d_in[11];
    const float* lnb  = (const float*)d_in[12];
    const float* opw  = (const float*)d_in[13];

    float* pool = nullptr;
    cudaGetSymbolAddress((void**)&pool, g_pool);
    float* xz    = pool + OFF_XZ;
    float* xc    = pool + OFF_XC;
    float* ycat  = pool + OFF_YCAT;
    float* delta = pool + OFF_DELTA;
    float* Bpp   = pool + OFF_BP;
    float* Cpp   = pool + OFF_CP;
    float* rW    = pool + OFF_RW;

    cudaFuncSetAttribute(gemm_tf32_mma,
                         cudaFuncAttributeMaxDynamicSharedMemorySize,
                         WG_SMEM_BYTES);

    // 1) round hs -> ycat region (free until conv), round ipw -> rW
    {
        int n4 = (BL * DM) / 4;
        round_tf32_kernel<<<(n4 + 255) / 256, 256>>>(hs, ycat, n4);
        int w4 = (DI * DM) / 4;
        round_tf32_kernel<<<(w4 + 255) / 256, 256>>>(ipw, rW, w4);
    }
    // 2) xz = r_hs @ r_ipw^T   [16384,1024]
    gemm_tf32_mma<<<dim3(DI / 128, BL / 128), 128, WG_SMEM_BYTES>>>(
        ycat, rW, xz, BL, DI, DM);
    // 3) depthwise conv + silu (x -> xc, z -> ycat[:,512:])
    conv_silu_kernel<<<BL, 256>>>(xz, cxw, cxb, czw, czb, xc, ycat);
    // 4) x_proj + LN + dt_proj + softplus
    k3_kernel<<<BL / 16, 256>>>(xc, xpw, dtw, dtb, lnw, lnb, delta, Bpp, Cpp);
    // 5) selective scan -> ycat[:, :512]
    scan_kernel<<<128, 256>>>(delta, xc, Bpp, Cpp, alog, Dp, ycat);
    // 6) round ycat -> xz region (free now), round opw -> rW
    {
        int n4 = (BL * DI) / 4;
        round_tf32_kernel<<<(n4 + 255) / 256, 256>>>(ycat, xz, n4);
        int w4 = (DM * DI) / 4;
        round_tf32_kernel<<<(w4 + 255) / 256, 256>>>(opw, rW, w4);
    }
    // 7) out = r_ycat @ r_opw^T  [16384,512]
    gemm_tf32_mma<<<dim3(DM / 128, BL / 128), 128, WG_SMEM_BYTES>>>(
        xz, rW, (float*)d_out, BL, DM, DI);
}

// round 10
// speedup vs baseline: 1.3945x; 1.1054x over previous
#include <cuda_runtime.h>
#include <cuda_fp16.h>
#include <cstdint>

// Problem constants
#define BSZ   4
#define SEQ   4096
#define BL    16384          // BSZ*SEQ tokens
#define DM    512            // d_model
#define DI    1024           // d_inner
#define DH    512            // d_half
#define DTR   32             // dt_rank
#define NST   16             // d_state
#define XDB   64             // dt_rank + 2*d_state

// Scratch pool (static device global: allocation-free at runtime)
// xc region doubles as fp16 activation buffer (BL*DH floats == BL*DI halves)
// delta region doubles as fp16 weight buffer (needs DI*DM halves = 256K floats)
#define OFF_XZ    0
#define OFF_XC    ((size_t)BL * DI)
#define OFF_YCAT  (OFF_XC + (size_t)BL * DH)
#define OFF_DELTA (OFF_YCAT + (size_t)BL * DI)
#define OFF_BP    (OFF_DELTA + (size_t)BL * DH)
#define OFF_CP    (OFF_BP + (size_t)BL * NST)
#define POOL_SZ   (OFF_CP + (size_t)BL * NST)
__device__ float g_pool[POOL_SZ];

// ---------------------------------------------------------------------------
// Helpers
// ---------------------------------------------------------------------------
__device__ __forceinline__ uint32_t sm_u32(const void* p) {
    return (uint32_t)__cvta_generic_to_shared(p);
}
__device__ __forceinline__ void cp16(uint32_t dst, const void* src) {
    asm volatile("cp.async.cg.shared.global [%0], [%1], 16;" :: "r"(dst), "l"(src));
}

// ---------------------------------------------------------------------------
// fp32 -> fp16 conversion (rn)
// ---------------------------------------------------------------------------
__global__ __launch_bounds__(256) void to_half_kernel(
    const float* __restrict__ in, __half* __restrict__ out, int n4)
{
    int i = blockIdx.x * 256 + threadIdx.x;
    if (i < n4) {
        float4 v = ((const float4*)in)[i];
        __half2 h0 = __floats2half2_rn(v.x, v.y);
        __half2 h1 = __floats2half2_rn(v.z, v.w);
        ((__half2*)out)[2 * i]     = h0;
        ((__half2*)out)[2 * i + 1] = h1;
    }
}

// ---------------------------------------------------------------------------
// FP16 mma.sync GEMM: C[M,N] = A[M,K] @ B[N,K]^T (fp16 in, fp32 out/acc)
// CTA 128x128, 4 warps (2x2), warp tile 64x64, BK=32 halves, 4-stage cp.async.
// Smem [row][k], row stride 40 halves (20 words) -> conflict-free frag loads.
// Requires M%128==0, N%128==0, K%32==0.
// ---------------------------------------------------------------------------
#define HG_RSH   40                        // halves per smem row
#define HG_OPB   (128 * HG_RSH * 2)        // bytes per operand per stage (10240)
#define HG_STAGES 4
#define HG_SMEM_BYTES (HG_STAGES * 2 * HG_OPB)   // 81920

__global__ __launch_bounds__(128, 1) void gemm_fp16_mma(
    const __half* __restrict__ A, const __half* __restrict__ B,
    float* __restrict__ C, int M, int N, int K)
{
    extern __shared__ uint32_t smw[];
    const int tid  = threadIdx.x;
    const int lane = tid & 31;
    const int wid  = tid >> 5;
    const int bm = blockIdx.y * 128;
    const int bn = blockIdx.x * 128;
    const int NC = K / 32;

    const int wm = (wid & 1) * 64;
    const int wn = (wid >> 1) * 64;
    const int r = lane >> 2;      // 0..7
    const int c = lane & 3;       // 0..3

    const uint32_t smb = sm_u32(smw);

    // per stage: A 512 chunks(16B) + B 512 chunks; 128 threads x 8
    auto load_chunk = [&](int chunk, int stage) {
        const int k0 = chunk * 32;
        const uint32_t aB = smb + stage * 2 * HG_OPB;
        const uint32_t bB = aB + HG_OPB;
#pragma unroll
        for (int j = 0; j < 8; j++) {
            int idx = tid + j * 128;          // 0..1023
            if (idx < 512) {
                int row = idx >> 2, seg = idx & 3;
                cp16(aB + row * 80 + seg * 16,
                     A + (size_t)(bm + row) * K + k0 + seg * 8);
            } else {
                int t = idx - 512;
                int row = t >> 2, seg = t & 3;
                cp16(bB + row * 80 + seg * 16,
                     B + (size_t)(bn + row) * K + k0 + seg * 8);
            }
        }
    };

    float acc[4][8][4];
#pragma unroll
    for (int i = 0; i < 4; i++)
#pragma unroll
        for (int j = 0; j < 8; j++)
#pragma unroll
            for (int q = 0; q < 4; q++) acc[i][j][q] = 0.f;

#pragma unroll
    for (int s = 0; s < HG_STAGES - 1; s++) {
        load_chunk(s, s);
        asm volatile("cp.async.commit_group;" ::: "memory");
    }

    for (int i = 0; i < NC; i++) {
        asm volatile("cp.async.wait_group %0;" :: "n"(HG_STAGES - 2) : "memory");
        __syncthreads();

        if (i + HG_STAGES - 1 < NC)
            load_chunk(i + HG_STAGES - 1, (i + HG_STAGES - 1) & (HG_STAGES - 1));
        asm volatile("cp.async.commit_group;" ::: "memory");

        const int st = i & (HG_STAGES - 1);
        const uint32_t* As = smw + st * (2 * HG_OPB / 4);
        const uint32_t* Bs = As + HG_OPB / 4;

#pragma unroll
        for (int g = 0; g < 2; g++) {          // two k16 groups per BK=32
            const int kw = g * 8;              // word offset within row
            uint32_t af[4][4], bf[8][2];
#pragma unroll
            for (int ii = 0; ii < 4; ii++) {
                const int m0 = wm + ii * 16;
                af[ii][0] = As[(m0 + r)     * 20 + kw + c];
                af[ii][1] = As[(m0 + r + 8) * 20 + kw + c];
                af[ii][2] = As[(m0 + r)     * 20 + kw + c + 4];
                af[ii][3] = As[(m0 + r + 8) * 20 + kw + c + 4];
            }
#pragma unroll
            for (int jj = 0; jj < 8; jj++) {
                const int n0 = wn + jj * 8;
                bf[jj][0] = Bs[(n0 + r) * 20 + kw + c];
                bf[jj][1] = Bs[(n0 + r) * 20 + kw + c + 4];
            }
#pragma unroll
            for (int ii = 0; ii < 4; ii++)
#pragma unroll
                for (int jj = 0; jj < 8; jj++) {
                    asm volatile(
                        "mma.sync.aligned.m16n8k16.row.col.f32.f16.f16.f32 "
                        "{%0,%1,%2,%3}, {%4,%5,%6,%7}, {%8,%9}, {%0,%1,%2,%3};"
                        : "+f"(acc[ii][jj][0]), "+f"(acc[ii][jj][1]),
                          "+f"(acc[ii][jj][2]), "+f"(acc[ii][jj][3])
                        : "r"(af[ii][0]), "r"(af[ii][1]),
                          "r"(af[ii][2]), "r"(af[ii][3]),
                          "r"(bf[jj][0]), "r"(bf[jj][1]));
                }
        }
        __syncthreads();
    }

    // epilogue: c0:(r,2c) c1:(r,2c+1) c2:(r+8,2c) c3:(r+8,2c+1)
#pragma unroll
    for (int i = 0; i < 4; i++) {
        const int row0 = bm + wm + i * 16 + r;
#pragma unroll
        for (int j = 0; j < 8; j++) {
            const int col = bn + wn + j * 8 + 2 * c;
            *(float2*)&C[(size_t)row0 * N + col] =
                make_float2(acc[i][j][0], acc[i][j][1]);
            *(float2*)&C[(size_t)(row0 + 8) * N + col] =
                make_float2(acc[i][j][2], acc[i][j][3]);
        }
    }
}

// ---------------------------------------------------------------------------
// Depthwise conv(k=4, pad l=1 r=2) + SiLU. Vectorized weight/bias loads.
// x half -> xc; z half -> ycat[:, 512:1024]
// ---------------------------------------------------------------------------
__global__ __launch_bounds__(256) void conv_silu_kernel(
    const float* __restrict__ xz,
    const float* __restrict__ cxw, const float* __restrict__ cxb,
    const float* __restrict__ czw, const float* __restrict__ czb,
    float* __restrict__ xcout, float* __restrict__ ycat)
{
    int idx = blockIdx.x * 256 + threadIdx.x;
    int c4 = idx & 255;
    int t  = idx >> 8;
    int l  = t & (SEQ - 1);
    int c  = c4 * 4;

    const float* base = xz + (size_t)t * DI + c;
    float4 z4 = make_float4(0.f, 0.f, 0.f, 0.f);
    float4 s0 = (l >= 1)       ? *(const float4*)(base - DI)     : z4;
    float4 s1 =                  *(const float4*)(base);
    float4 s2 = (l + 1 < SEQ)  ? *(const float4*)(base + DI)     : z4;
    float4 s3 = (l + 2 < SEQ)  ? *(const float4*)(base + 2 * DI) : z4;

    float r0[4], r1[4], r2[4], r3[4];
    *(float4*)r0 = s0; *(float4*)r1 = s1; *(float4*)r2 = s2; *(float4*)r3 = s3;

    const bool isx = (c < DH);
    const int  cc  = isx ? c : (c - DH);
    const float* w  = (isx ? cxw : czw) + cc * 4;   // 16 consecutive floats
    const float* bb = (isx ? cxb : czb) + cc;       // 4 consecutive floats

    float Wf[16], Bf[4];
    *(float4*)(Wf + 0)  = *(const float4*)(w + 0);
    *(float4*)(Wf + 4)  = *(const float4*)(w + 4);
    *(float4*)(Wf + 8)  = *(const float4*)(w + 8);
    *(float4*)(Wf + 12) = *(const float4*)(w + 12);
    *(float4*)Bf        = *(const float4*)(bb);

    float out[4];
#pragma unroll
    for (int i = 0; i < 4; i++) {
        float v = Bf[i]
                + Wf[i * 4 + 0] * r0[i]
                + Wf[i * 4 + 1] * r1[i]
                + Wf[i * 4 + 2] * r2[i]
                + Wf[i * 4 + 3] * r3[i];
        float sg = __fdividef(1.f, 1.f + __expf(-v));
        out[i] = v * sg;
    }
    if (isx) *(float4*)(xcout + (size_t)t * DH + c) = *(float4*)out;
    else     *(float4*)(ycat  + (size_t)t * DI + c) = *(float4*)out;
}

// ---------------------------------------------------------------------------
// Fused: x_dbl = xc @ x_proj_w^T (64), LN(64), split Bp/Cp,
//        dt = clip(dt_raw @ dt_proj_w^T,-6,6), delta = softplus(dt+bias)
// ---------------------------------------------------------------------------
__global__ __launch_bounds__(256) void k3_kernel(
    const float* __restrict__ xc,  const float* __restrict__ xpw,
    const float* __restrict__ dtw, const float* __restrict__ dtb,
    const float* __restrict__ lnw, const float* __restrict__ lnb,
    float* __restrict__ delta, float* __restrict__ Bp, float* __restrict__ Cp)
{
    __shared__ float s_xc[16][DH];
    __shared__ float s_db[16][XDB];

    const int tid = threadIdx.x;
    const size_t tok0 = (size_t)blockIdx.x * 16;

    {
        const float4* src = (const float4*)(xc + tok0 * DH);
        float4* dst = (float4*)&s_xc[0][0];
#pragma unroll
        for (int i = 0; i < 8; i++) dst[tid + i * 256] = src[tid + i * 256];
    }
    __syncthreads();

    {
        const int j  = tid & 63;
        const int tg = tid >> 6;
        const float4* wr = (const float4*)(xpw + (size_t)j * DH);
        const float4* x0 = (const float4*)&s_xc[tg * 4 + 0][0];
        const float4* x1 = (const float4*)&s_xc[tg * 4 + 1][0];
        const float4* x2 = (const float4*)&s_xc[tg * 4 + 2][0];
        const float4* x3 = (const float4*)&s_xc[tg * 4 + 3][0];
        float a0 = 0.f, a1 = 0.f, a2 = 0.f, a3 = 0.f;
#pragma unroll 4
        for (int k = 0; k < DH / 4; k++) {
            float4 w4 = wr[k];
            float4 v0 = x0[k], v1 = x1[k], v2 = x2[k], v3 = x3[k];
            a0 += w4.x * v0.x + w4.y * v0.y + w4.z * v0.z + w4.w * v0.w;
            a1 += w4.x * v1.x + w4.y * v1.y + w4.z * v1.z + w4.w * v1.w;
            a2 += w4.x * v2.x + w4.y * v2.y + w4.z * v2.z + w4.w * v2.w;
            a3 += w4.x * v3.x + w4.y * v3.y + w4.z * v3.z + w4.w * v3.w;
        }
        s_db[tg * 4 + 0][j] = a0;
        s_db[tg * 4 + 1][j] = a1;
        s_db[tg * 4 + 2][j] = a2;
        s_db[tg * 4 + 3][j] = a3;
    }
    __syncthreads();

    {
        const int tok = tid >> 4;
        const int q   = tid & 15;
        const int j0  = q * 4;
        float v0 = s_db[tok][j0], v1 = s_db[tok][j0 + 1];
        float v2 = s_db[tok][j0 + 2], v3 = s_db[tok][j0 + 3];
        float s = v0 + v1 + v2 + v3;
        s += __shfl_xor_sync(0xffffffffu, s, 1);
        s += __shfl_xor_sync(0xffffffffu, s, 2);
        s += __shfl_xor_sync(0xffffffffu, s, 4);
        s += __shfl_xor_sync(0xffffffffu, s, 8);
        float mu = s * (1.f / 64.f);
        float d0 = v0 - mu, d1 = v1 - mu, d2 = v2 - mu, d3 = v3 - mu;
        float sq = d0 * d0 + d1 * d1 + d2 * d2 + d3 * d3;
        sq += __shfl_xor_sync(0xffffffffu, sq, 1);
        sq += __shfl_xor_sync(0xffffffffu, sq, 2);
        sq += __shfl_xor_sync(0xffffffffu, sq, 4);
        sq += __shfl_xor_sync(0xffffffffu, sq, 8);
        float rstd = rsqrtf(sq * (1.f / 64.f) + 1e-5f);
        float o[4];
        o[0] = d0 * rstd * lnw[j0]     + lnb[j0];
        o[1] = d1 * rstd * lnw[j0 + 1] + lnb[j0 + 1];
        o[2] = d2 * rstd * lnw[j0 + 2] + lnb[j0 + 2];
        o[3] = d3 * rstd * lnw[j0 + 3] + lnb[j0 + 3];
        s_db[tok][j0] = o[0]; s_db[tok][j0 + 1] = o[1];
        s_db[tok][j0 + 2] = o[2]; s_db[tok][j0 + 3] = o[3];
        if (q >= 8) {
            size_t tk = tok0 + tok;
            int base = j0 - DTR;
#pragma unroll
            for (int i = 0; i < 4; i++) {
                int jj = base + i;
                if (jj < NST) Bp[tk * NST + jj]         = o[i];
                else          Cp[tk * NST + (jj - NST)] = o[i];
            }
        }
    }
    __syncthreads();

    {
#pragma unroll
        for (int half = 0; half < 2; half++) {
            const int dch = tid + half * 256;
            const float4* wr = (const float4*)(dtw + (size_t)dch * DTR);
            float4 w4[8];
#pragma unroll
            for (int i = 0; i < 8; i++) w4[i] = wr[i];
            const float bias = dtb[dch];
#pragma unroll
            for (int tok = 0; tok < 16; tok++) {
                const float4* xr = (const float4*)&s_db[tok][0];
                float acc = 0.f;
#pragma unroll
                for (int i = 0; i < 8; i++) {
                    float4 x4 = xr[i];
                    acc += w4[i].x * x4.x + w4[i].y * x4.y
                         + w4[i].z * x4.z + w4[i].w * x4.w;
                }
                float v = fminf(fmaxf(acc, -6.f), 6.f) + bias;
                float sp = fmaxf(v, 0.f) + log1pf(__expf(-fabsf(v)));
                delta[(tok0 + tok) * (size_t)DH + dch] = sp;
            }
        }
    }
}

// ---------------------------------------------------------------------------
// Selective scan. Channel (b,d) = 16 lanes (one per state), 2 channels/warp.
// ---------------------------------------------------------------------------
__global__ __launch_bounds__(256) void scan_kernel(
    const float* __restrict__ delta, const float* __restrict__ xc,
    const float* __restrict__ Bp,    const float* __restrict__ Cp,
    const float* __restrict__ A_log, const float* __restrict__ D_param,
    float* __restrict__ ycat)
{
    const int tid = threadIdx.x;
    const int ch  = blockIdx.x * 16 + (tid >> 4);
    const int n   = tid & 15;
    const int b   = ch >> 9;
    const int d   = ch & 511;

    const float a  = -__expf(A_log[d * NST + n]);
    const float Dd = D_param[d];

    const float* dl = delta + ((size_t)b * SEQ) * DH + d;
    const float* ul = xc    + ((size_t)b * SEQ) * DH + d;
    const float* Bl = Bp    + ((size_t)b * SEQ) * NST + n;
    const float* Cl = Cp    + ((size_t)b * SEQ) * NST + n;
    float*       yl = ycat  + ((size_t)b * SEQ) * DI + d;

    float h = 0.f;
    float dv[2][4], uv[2][4], bv[2][4], cv[2][4];

#pragma unroll
    for (int i = 0; i < 4; i++) {
        dv[0][i] = dl[i * DH];  uv[0][i] = ul[i * DH];
        bv[0][i] = Bl[i * NST]; cv[0][i] = Cl[i * NST];
    }

    for (int l0 = 0; l0 < SEQ; l0 += 4) {
        const int cur = (l0 >> 2) & 1;
        const int nxt = cur ^ 1;
        if (l0 + 4 < SEQ) {
            const float* dn = dl + 4 * DH;
            const float* un = ul + 4 * DH;
            const float* bn = Bl + 4 * NST;
            const float* cn = Cl + 4 * NST;
#pragma unroll
            for (int i = 0; i < 4; i++) {
                dv[nxt][i] = dn[i * DH];  uv[nxt][i] = un[i * DH];
                bv[nxt][i] = bn[i * NST]; cv[nxt][i] = cn[i * NST];
            }
        }
#pragma unroll
        for (int i = 0; i < 4; i++) {
            float dvi = dv[cur][i];
            float da  = __expf(dvi * a);
            h = fmaf(da, h, dvi * uv[cur][i] * bv[cur][i]);
            float p = h * cv[cur][i];
            p += __shfl_xor_sync(0xffffffffu, p, 8);
            p += __shfl_xor_sync(0xffffffffu, p, 4);
            p += __shfl_xor_sync(0xffffffffu, p, 2);
            p += __shfl_xor_sync(0xffffffffu, p, 1);
            if (n == 0) yl[i * DI] = fmaf(Dd, uv[cur][i], p);
        }
        dl += 4 * DH; ul += 4 * DH; Bl += 4 * NST; Cl += 4 * NST; yl += 4 * DI;
    }
}

// ---------------------------------------------------------------------------
extern "C" void kernel_launch(void* const* d_in, const int* in_sizes, int n_in,
                              void* d_out, int out_size)
{
    const float* hs   = (const float*)d_in[0];
    const float* ipw  = (const float*)d_in[1];
    const float* xpw  = (const float*)d_in[2];
    const float* dtw  = (const float*)d_in[3];
    const float* dtb  = (const float*)d_in[4];
    const float* alog = (const float*)d_in[5];
    const float* Dp   = (const float*)d_in[6];
    const float* cxw  = (const float*)d_in[7];
    const float* cxb  = (const float*)d_in[8];
    const float* czw  = (const float*)d_in[9];
    const float* czb  = (const float*)d_in[10];
    const float* lnw  = (const float*)d_in[11];
    const float* lnb  = (const float*)d_in[12];
    const float* opw  = (const float*)d_in[13];

    float* pool = nullptr;
    cudaGetSymbolAddress((void**)&pool, g_pool);
    float* xz    = pool + OFF_XZ;
    float* xc    = pool + OFF_XC;
    float* ycat  = pool + OFF_YCAT;
    float* delta = pool + OFF_DELTA;
    float* Bpp   = pool + OFF_BP;
    float* Cpp   = pool + OFF_CP;
    // fp16 aliases (regions free at their time of use; see layout comment)
    __half* hAct = (__half*)xc;      // activations (<= BL*DI halves)
    __half* hW   = (__half*)delta;   // weights     (<= DI*DM halves)

    cudaFuncSetAttribute(gemm_fp16_mma,
                         cudaFuncAttributeMaxDynamicSharedMemorySize,
                         HG_SMEM_BYTES);

    // 1) halve inputs for GEMM1 (xc region free until conv; delta free until k3)
    to_half_kernel<<<(BL * DM / 4 + 255) / 256, 256>>>(hs, hAct, BL * DM / 4);
    to_half_kernel<<<(DI * DM / 4 + 255) / 256, 256>>>(ipw, hW, DI * DM / 4);
    // 2) xz = hs @ ipw^T   [16384,1024]
    gemm_fp16_mma<<<dim3(DI / 128, BL / 128), 128, HG_SMEM_BYTES>>>(
        hAct, hW, xz, BL, DI, DM);
    // 3) depthwise conv + silu (x -> xc, z -> ycat[:,512:])
    conv_silu_kernel<<<BL, 256>>>(xz, cxw, cxb, czw, czb, xc, ycat);
    // 4) x_proj + LN + dt_proj + softplus
    k3_kernel<<<BL / 16, 256>>>(xc, xpw, dtw, dtb, lnw, lnb, delta, Bpp, Cpp);
    // 5) selective scan -> ycat[:, :512]
    scan_kernel<<<128, 256>>>(delta, xc, Bpp, Cpp, alog, Dp, ycat);
    // 6) halve inputs for GEMM2 (xc consumed by scan; delta consumed by scan)
    to_half_kernel<<<(BL * DI / 4 + 255) / 256, 256>>>(ycat, hAct, BL * DI / 4);
    to_half_kernel<<<(DM * DI / 4 + 255) / 256, 256>>>(opw, hW, DM * DI / 4);
    // 7) out = ycat @ opw^T  [16384,512]
    gemm_fp16_mma<<<dim3(DM / 128, BL / 128), 128, HG_SMEM_BYTES>>>(
        hAct, hW, (float*)d_out, BL, DM, DI);
}